// round 3
// baseline (speedup 1.0000x reference)
#include <cuda_runtime.h>
#include <cuda_bf16.h>
#include <cstdint>

// NPSCalculator: nps = sum_{b,h,w} min_k sqrt( sum_c (x[b,c,h,w] - p[k,c] + 1e-6)^2 + 1e-6 ) / size
// B=8, C=3, H=512, W=512, NUM_COLORS=30.
//
// R3: latency/occupancy attack (R2 showed fma pipe was NOT the limiter).
//  - 4 px/thread (2 packed pairs), 2048 blocks x 256 threads -> ~6 resident blocks/SM
//    (~48 warps, 75% occ) vs R2's 3.46 blocks/SM (34% occ).
//  - dist^2 = ssq_pixel + (2v)·x + sum v^2 ; min over k before sqrt.
//  - fused fma2+unpack asm so ptxas aliases the mov.b64 (no ALU cost).
//  - single launch: per-block partials + wrap-around atomicInc last-block reduce.

#define HW_       262144
#define CHW_      (3 * HW_)
#define THREADS_  256
#define BLOCKS_   2048
#define INV_SIZE_ (1.0f / 6291456.0f)

typedef unsigned long long u64;

__device__ float        g_partial[BLOCKS_];
__device__ unsigned int g_count = 0;

__device__ __forceinline__ u64 f2pk(float lo, float hi) {
    u64 r; asm("mov.b64 %0, {%1, %2};" : "=l"(r) : "f"(lo), "f"(hi)); return r;
}
__device__ __forceinline__ void f2unpk(u64 v, float& lo, float& hi) {
    asm("mov.b64 {%0, %1}, %2;" : "=f"(lo), "=f"(hi) : "l"(v));
}
__device__ __forceinline__ u64 fma2(u64 a, u64 b, u64 c) {
    u64 r; asm("fma.rn.f32x2 %0, %1, %2, %3;" : "=l"(r) : "l"(a), "l"(b), "l"(c)); return r;
}
// fused: {lo,hi} = a*b + c  (unpack aliased by ptxas, no extra SASS movs)
__device__ __forceinline__ void fma2u(u64 a, u64 b, u64 c, float& lo, float& hi) {
    asm("{\n\t.reg .b64 t;\n\tfma.rn.f32x2 t, %2, %3, %4;\n\tmov.b64 {%0, %1}, t;\n\t}"
        : "=f"(lo), "=f"(hi) : "l"(a), "l"(b), "l"(c));
}

__global__ __launch_bounds__(THREADS_, 6)
void nps_kernel(const float* __restrict__ adv,
                const float* __restrict__ prn,
                float* __restrict__ out)
{
    // [k][0] = {W0, W1}, [k][1] = {W2, C};  W_c = 2*(1e-6 - p_kc) dup'd, C = sum v^2 dup'd
    __shared__ ulonglong2 shWC[60];
    __shared__ float      shRed[8];
    __shared__ int        shLast;

    int tid = threadIdx.x;
    if (tid < 30) {
        float v0 = 1e-6f - prn[tid * 3 + 0];
        float v1 = 1e-6f - prn[tid * 3 + 1];
        float v2 = 1e-6f - prn[tid * 3 + 2];
        float c  = v0 * v0 + v1 * v1 + v2 * v2;
        shWC[tid * 2 + 0] = make_ulonglong2(f2pk(2.f * v0, 2.f * v0),
                                            f2pk(2.f * v1, 2.f * v1));
        shWC[tid * 2 + 1] = make_ulonglong2(f2pk(2.f * v2, 2.f * v2),
                                            f2pk(c, c));
    }
    __syncthreads();

    // one float4-group (4 pixels) per thread
    int g  = blockIdx.x * THREADS_ + tid;          // 0 .. 524287
    int p4 = g * 4;
    const float4* q = reinterpret_cast<const float4*>(
        adv + (size_t)(p4 >> 18) * CHW_ + (p4 & (HW_ - 1)));
    float4 a0 = q[0];
    float4 a1 = q[HW_ / 4];
    float4 a2 = q[2 * (HW_ / 4)];

    u64 XA0 = f2pk(a0.x, a0.y), XA1 = f2pk(a1.x, a1.y), XA2 = f2pk(a2.x, a2.y);
    u64 XB0 = f2pk(a0.z, a0.w), XB1 = f2pk(a1.z, a1.w), XB2 = f2pk(a2.z, a2.w);

    const u64 EPS2 = f2pk(1e-6f, 1e-6f);
    // per-pixel sum of squares + 1e-6 (constant over colors)
    u64 sA = fma2(XA0, XA0, EPS2); sA = fma2(XA1, XA1, sA); sA = fma2(XA2, XA2, sA);
    u64 sB = fma2(XB0, XB0, EPS2); sB = fma2(XB1, XB1, sB); sB = fma2(XB2, XB2, sB);

    float mA0, mA1, mB0, mB1;
    {   // k = 0 peeled: initializes the mins
        ulonglong2 w01 = shWC[0];
        ulonglong2 w2c = shWC[1];
        u64 acc;
        acc = fma2(w01.x, XA0, w2c.y); acc = fma2(w01.y, XA1, acc);
        fma2u(w2c.x, XA2, acc, mA0, mA1);
        acc = fma2(w01.x, XB0, w2c.y); acc = fma2(w01.y, XB1, acc);
        fma2u(w2c.x, XB2, acc, mB0, mB1);
    }

    #pragma unroll 29
    for (int k = 1; k < 30; k++) {
        ulonglong2 w01 = shWC[k * 2 + 0];
        ulonglong2 w2c = shWC[k * 2 + 1];
        float lo, hi;
        u64 acc;

        acc = fma2(w01.x, XA0, w2c.y); acc = fma2(w01.y, XA1, acc);
        fma2u(w2c.x, XA2, acc, lo, hi);
        mA0 = fminf(mA0, lo); mA1 = fminf(mA1, hi);

        acc = fma2(w01.x, XB0, w2c.y); acc = fma2(w01.y, XB1, acc);
        fma2u(w2c.x, XB2, acc, lo, hi);
        mB0 = fminf(mB0, lo); mB1 = fminf(mB1, hi);
    }

    float sAl, sAh, sBl, sBh;
    f2unpk(sA, sAl, sAh); f2unpk(sB, sBl, sBh);

    float tsum = sqrtf(mA0 + sAl) + sqrtf(mA1 + sAh)
               + sqrtf(mB0 + sBl) + sqrtf(mB1 + sBh);

    // warp reduce
    #pragma unroll
    for (int off = 16; off > 0; off >>= 1)
        tsum += __shfl_xor_sync(0xffffffffu, tsum, off);
    if ((tid & 31) == 0) shRed[tid >> 5] = tsum;
    __syncthreads();

    if (tid == 0) {
        float bs = shRed[0] + shRed[1] + shRed[2] + shRed[3]
                 + shRed[4] + shRed[5] + shRed[6] + shRed[7];
        g_partial[blockIdx.x] = bs;
        __threadfence();
        unsigned int prev = atomicInc(&g_count, BLOCKS_ - 1);
        shLast = (prev == BLOCKS_ - 1);
    }
    __syncthreads();

    if (shLast) {
        volatile float* vp = g_partial;
        float s = 0.0f;
        #pragma unroll
        for (int i = 0; i < BLOCKS_ / THREADS_; i++)
            s += vp[tid + i * THREADS_];
        #pragma unroll
        for (int off = 16; off > 0; off >>= 1)
            s += __shfl_xor_sync(0xffffffffu, s, off);
        if ((tid & 31) == 0) shRed[tid >> 5] = s;
        __syncthreads();
        if (tid == 0) {
            float tot = shRed[0] + shRed[1] + shRed[2] + shRed[3]
                      + shRed[4] + shRed[5] + shRed[6] + shRed[7];
            out[0] = tot * INV_SIZE_;
        }
    }
}

extern "C" void kernel_launch(void* const* d_in, const int* in_sizes, int n_in,
                              void* d_out, int out_size)
{
    const float* adv = (const float*)d_in[0];   // (8,3,512,512) f32
    const float* prn = (const float*)d_in[1];   // (30,3) f32
    nps_kernel<<<BLOCKS_, THREADS_>>>(adv, prn, (float*)d_out);
}